// round 2
// baseline (speedup 1.0000x reference)
#include <cuda_runtime.h>
#include <cuda_bf16.h>
#include <cstdint>

#define N_NODES 100000
#define DIMH 128

// -------- scratch (device globals; no allocation allowed) --------
__device__ __align__(16) float g_aggr[(size_t)N_NODES * DIMH];
__device__ __align__(16) float g_h1[(size_t)N_NODES * DIMH];
__device__ __align__(16) float g_xw[(size_t)N_NODES * DIMH];
__device__ float g_dinv[N_NODES];
__device__ int   g_deg[N_NODES];
__device__ int   g_is64;

// -------- packed f32x2 helpers (2x fp32 FMA throughput on sm_103a) --------
__device__ __forceinline__ unsigned long long pack2(float a, float b) {
    unsigned long long r;
    asm("mov.b64 %0, {%1,%2};" : "=l"(r) : "f"(a), "f"(b));
    return r;
}
__device__ __forceinline__ void ffma2(unsigned long long& d, unsigned long long a, unsigned long long b) {
    asm("fma.rn.f32x2 %0, %1, %2, %0;" : "+l"(d) : "l"(a), "l"(b));
}
__device__ __forceinline__ float2 unpack2(unsigned long long v) {
    float2 r;
    asm("mov.b64 {%0,%1}, %2;" : "=f"(r.x), "=f"(r.y) : "l"(v));
    return r;
}

// vector reduction to global (no return) — 4 floats per L2 atomic op
__device__ __forceinline__ void red_add_v4(float* addr, float4 v) {
    asm volatile("red.global.add.v4.f32 [%0], {%1,%2,%3,%4};"
                 :: "l"(addr), "f"(v.x), "f"(v.y), "f"(v.z), "f"(v.w)
                 : "memory");
}

// -------- dtype detection: int64 edge_index has zero odd words --------
__global__ void k_detect(const unsigned int* __restrict__ w) {
    __shared__ int nz;
    if (threadIdx.x == 0) nz = 0;
    __syncthreads();
    if (w[threadIdx.x * 2 + 1] != 0u) atomicOr(&nz, 1);
    __syncthreads();
    if (threadIdx.x == 0) g_is64 = (nz == 0) ? 1 : 0;
}

// edge index fetch honoring detected dtype
__device__ __forceinline__ void load_edge(const void* ei, int E, int e, int& s, int& d) {
    if (g_is64) {
        s = (int)__ldg((const long long*)ei + e);
        d = (int)__ldg((const long long*)ei + E + e);
    } else {
        s = __ldg((const int*)ei + e);
        d = __ldg((const int*)ei + E + e);
    }
}

// -------- zero scratch --------
__global__ void k_zero() {
    int i = blockIdx.x * 256 + threadIdx.x;
    if (i < N_NODES * 32) ((float4*)g_aggr)[i] = make_float4(0.f, 0.f, 0.f, 0.f);
    if (i < N_NODES) g_deg[i] = 0;
}

// -------- edge pass 1: aggr[dst] += x[src]; deg[dst]++ --------
__global__ __launch_bounds__(256) void k_gin_scatter(const float* __restrict__ x,
                                                     const void* __restrict__ ei, int E) {
    long long idx = (long long)blockIdx.x * blockDim.x + threadIdx.x;
    int e = (int)(idx >> 5);
    if (e >= E) return;
    int lane = (int)(idx & 31);
    int s, d;
    load_edge(ei, E, e, s, d);
    float4 v = __ldg((const float4*)x + (size_t)s * 32 + lane);
    red_add_v4(g_aggr + (size_t)d * DIMH + lane * 4, v);
    if (lane == 0) atomicAdd(&g_deg[d], 1);
}

__global__ void k_dinv() {
    int i = blockIdx.x * 256 + threadIdx.x;
    if (i < N_NODES) g_dinv[i] = rsqrtf((float)g_deg[i] + 1.0f);
}

// -------- shared-mem row-tile GEMM core: 1 node row x 16 cols per thread ----
__device__ __forceinline__ void gemm_rowtile(const float* __restrict__ inrow,
                                             const float* __restrict__ Ws,
                                             int cg, float o[16]) {
    unsigned long long acc[8];
#pragma unroll
    for (int j = 0; j < 8; j++) acc[j] = 0ULL;
#pragma unroll 4
    for (int k = 0; k < 128; k++) {
        float a = inrow[k];
        unsigned long long a2 = pack2(a, a);
        const ulonglong2* w = (const ulonglong2*)(Ws + k * 128 + cg * 16);
        ulonglong2 p0 = w[0], p1 = w[1], p2 = w[2], p3 = w[3];
        ffma2(acc[0], a2, p0.x); ffma2(acc[1], a2, p0.y);
        ffma2(acc[2], a2, p1.x); ffma2(acc[3], a2, p1.y);
        ffma2(acc[4], a2, p2.x); ffma2(acc[5], a2, p2.y);
        ffma2(acc[6], a2, p3.x); ffma2(acc[7], a2, p3.y);
    }
#pragma unroll
    for (int j = 0; j < 8; j++) {
        float2 f = unpack2(acc[j]);
        o[2 * j] = f.x; o[2 * j + 1] = f.y;
    }
}

// -------- MLP layer 1: h1 = relu(BN((x + aggr) @ W1 + b1)) --------
__global__ __launch_bounds__(256) void k_mlp1(const float* __restrict__ x,
                                              const float* __restrict__ W1,
                                              const float* __restrict__ b1,
                                              const float* __restrict__ gamma,
                                              const float* __restrict__ beta,
                                              const float* __restrict__ rmean,
                                              const float* __restrict__ rvar) {
    extern __shared__ float sm[];
    float* Ws = sm;                  // 16384
    float* ins = Ws + 16384;         // 32*129 = 4128
    float* scale_s = ins + 4128;     // 128
    float* shift_s = scale_s + 128;  // 128
    int tid = threadIdx.x;

    const float4* W4 = (const float4*)W1;
    float4* Ws4 = (float4*)Ws;
    for (int i = tid; i < 4096; i += 256) Ws4[i] = W4[i];
    if (tid < 128) {
        float sc = gamma[tid] * rsqrtf(rvar[tid] + 1e-5f);
        scale_s[tid] = sc;
        shift_s[tid] = (b1[tid] - rmean[tid]) * sc + beta[tid];
    }
    int node0 = blockIdx.x << 5;
    for (int i = tid; i < 1024; i += 256) {
        int n = i >> 5, q = i & 31;
        float4 a = ((const float4*)x)[(size_t)(node0 + n) * 32 + q];
        float4 b = ((const float4*)g_aggr)[(size_t)(node0 + n) * 32 + q];
        float* p = ins + n * 129 + q * 4;
        p[0] = a.x + b.x; p[1] = a.y + b.y; p[2] = a.z + b.z; p[3] = a.w + b.w;
    }
    __syncthreads();

    int nl = tid >> 3, cg = tid & 7;
    float o[16];
    gemm_rowtile(ins + nl * 129, Ws, cg, o);

    int node = node0 + nl;
    float2* hp = (float2*)g_h1 + (size_t)node * 64 + cg * 8;
#pragma unroll
    for (int j = 0; j < 8; j++) {
        int c = cg * 16 + 2 * j;
        float v0 = fmaxf(o[2 * j] * scale_s[c] + shift_s[c], 0.f);
        float v1 = fmaxf(o[2 * j + 1] * scale_s[c + 1] + shift_s[c + 1], 0.f);
        hp[j] = make_float2(v0, v1);
    }
}

// -------- MLP layer 2 + fused dual-GCN projection --------
__global__ __launch_bounds__(256) void k_mlp2(const float* __restrict__ W2,
                                              const float* __restrict__ b2,
                                              const float* __restrict__ Wmu,
                                              const float* __restrict__ bmu,
                                              const float* __restrict__ Wls,
                                              const float* __restrict__ bls,
                                              float* __restrict__ out) {
    extern __shared__ float sm[];
    float* W2s = sm;               // 16384
    float* Wcs = W2s + 16384;      // 16384
    float* ins = Wcs + 16384;      // 4128
    float* h2s = ins + 4128;       // 4128
    float* b2s = h2s + 4128;       // 128
    float* bcs = b2s + 128;        // 128
    int tid = threadIdx.x;

    float4* W2s4 = (float4*)W2s;
    const float4* W24 = (const float4*)W2;
    for (int i = tid; i < 4096; i += 256) W2s4[i] = W24[i];
    float4* Wcs4 = (float4*)Wcs;
    const float4* Wmu4 = (const float4*)Wmu;
    const float4* Wls4 = (const float4*)Wls;
    for (int i = tid; i < 2048; i += 256) {
        int k = i >> 4, q = i & 15;
        Wcs4[k * 32 + q] = Wmu4[i];
        Wcs4[k * 32 + 16 + q] = Wls4[i];
    }
    if (tid < 128) {
        b2s[tid] = b2[tid];
        bcs[tid] = (tid < 64) ? bmu[tid] : bls[tid - 64];
    }
    int node0 = blockIdx.x << 5;
    for (int i = tid; i < 1024; i += 256) {
        int n = i >> 5, q = i & 31;
        float4 a = ((const float4*)g_h1)[(size_t)(node0 + n) * 32 + q];
        float* p = ins + n * 129 + q * 4;
        p[0] = a.x; p[1] = a.y; p[2] = a.z; p[3] = a.w;
    }
    __syncthreads();

    int nl = tid >> 3, cg = tid & 7;
    float o[16];
    gemm_rowtile(ins + nl * 129, W2s, cg, o);
    {
        float* hp = h2s + nl * 129 + cg * 16;
#pragma unroll
        for (int j = 0; j < 16; j++) {
            int c = cg * 16 + j;
            hp[j] = fmaxf(o[j] + b2s[c], 0.f);
        }
    }
    __syncthreads();
    gemm_rowtile(h2s + nl * 129, Wcs, cg, o);

    int node = node0 + nl;
    float di = g_dinv[node];
    float d2 = di * di;
    float2* xp = (float2*)g_xw + (size_t)node * 64 + cg * 8;
    float* ob = (cg < 4)
        ? (out + (size_t)node * 64 + cg * 16)
        : (out + (size_t)N_NODES * 64 + (size_t)node * 64 + (cg - 4) * 16);
#pragma unroll
    for (int j = 0; j < 8; j++) {
        int c = cg * 16 + 2 * j;
        float x0 = o[2 * j], x1 = o[2 * j + 1];
        xp[j] = make_float2(x0, x1);
        ((float2*)ob)[j] = make_float2(x0 * d2 + bcs[c], x1 * d2 + bcs[c + 1]);
    }
}

// -------- edge pass 2: out[dst] += dinv[src]*dinv[dst] * xw[src] --------
__global__ __launch_bounds__(256) void k_gcn_scatter(const void* __restrict__ ei, int E,
                                                     float* __restrict__ out) {
    long long idx = (long long)blockIdx.x * blockDim.x + threadIdx.x;
    int e = (int)(idx >> 5);
    if (e >= E) return;
    int lane = (int)(idx & 31);
    int s, d;
    load_edge(ei, E, e, s, d);
    float w = g_dinv[s] * g_dinv[d];
    float4 v = __ldg((const float4*)g_xw + (size_t)s * 32 + lane);
    v.x *= w; v.y *= w; v.z *= w; v.w *= w;
    int c0 = lane * 4;
    float* base = (c0 < 64)
        ? (out + (size_t)d * 64 + c0)
        : (out + (size_t)N_NODES * 64 + (size_t)d * 64 + (c0 - 64));
    red_add_v4(base, v);
}

extern "C" void kernel_launch(void* const* d_in, const int* in_sizes, int n_in,
                              void* d_out, int out_size) {
    const float* x        = (const float*)d_in[0];
    const void*  ei       = (const void*)d_in[1];
    const float* W1       = (const float*)d_in[2];
    const float* b1       = (const float*)d_in[3];
    const float* gamma    = (const float*)d_in[4];
    const float* beta     = (const float*)d_in[5];
    const float* rmean    = (const float*)d_in[6];
    const float* rvar     = (const float*)d_in[7];
    const float* W2       = (const float*)d_in[8];
    const float* b2       = (const float*)d_in[9];
    const float* Wmu      = (const float*)d_in[10];
    const float* bmu      = (const float*)d_in[11];
    const float* Wls      = (const float*)d_in[12];
    const float* bls      = (const float*)d_in[13];
    float* out = (float*)d_out;

    int E = in_sizes[1] / 2;

    const int SMEM1 = (16384 + 4128 + 256) * 4;            // 83072 B
    const int SMEM2 = (16384 * 2 + 4128 * 2 + 256) * 4;    // 165120 B
    cudaFuncSetAttribute(k_mlp1, cudaFuncAttributeMaxDynamicSharedMemorySize, SMEM1);
    cudaFuncSetAttribute(k_mlp2, cudaFuncAttributeMaxDynamicSharedMemorySize, SMEM2);

    int edge_blocks = (int)(((long long)E * 32 + 255) / 256);

    k_detect<<<1, 256>>>((const unsigned int*)ei);
    k_zero<<<(N_NODES * 32 + 255) / 256, 256>>>();
    k_gin_scatter<<<edge_blocks, 256>>>(x, ei, E);
    k_dinv<<<(N_NODES + 255) / 256, 256>>>();
    k_mlp1<<<N_NODES / 32, 256, SMEM1>>>(x, W1, b1, gamma, beta, rmean, rvar);
    k_mlp2<<<N_NODES / 32, 256, SMEM2>>>(W2, b2, Wmu, bmu, Wls, bls, out);
    k_gcn_scatter<<<edge_blocks, 256>>>(ei, E, out);
}